// round 13
// baseline (speedup 1.0000x reference)
#include <cuda_runtime.h>

// CapsuleBlock: B=64, N=2048, D_in=8, K=16, O=16, 3 routing iters.
// R13: R11 (best, 68.4us) with the route wave-quantization fix: 4096 blocks
// of 32 n each (was 1024 x 128 n) -> tail shrinks from ~1.0 to ~0.3
// block-times at 6 resident blocks/SM. Route body/regs unchanged from R11.

#define NBLK  148
#define CHUNK 14           // 148*14 = 2072 >= 2048
#define GCH   64           // route g-chunks (32 n each)

__device__ float g_part [(size_t)NBLK * 16384];  // pass1 partials [blk][b][k][o]
__device__ float g_part2[(size_t)GCH * 16384];   // route partials [g][b][k][o]
__device__ float g_route[16384];                 // routing vector [b][k][o]
__device__ __align__(16) unsigned short g_hats[(size_t)64 * 2048 * 256]; // fp16 [b][n][k][o]

typedef unsigned long long ull;

__device__ __forceinline__ ull pack2(float v) {
    ull r; asm("mov.b64 %0, {%1, %1};" : "=l"(r) : "f"(v)); return r;
}
__device__ __forceinline__ ull fma2(ull a, ull b, ull c) {
    ull d; asm("fma.rn.f32x2 %0, %1, %2, %3;" : "=l"(d) : "l"(a), "l"(b), "l"(c)); return d;
}
__device__ __forceinline__ ull mul2(ull a, ull b) {
    ull d; asm("mul.rn.f32x2 %0, %1, %2;" : "=l"(d) : "l"(a), "l"(b)); return d;
}
__device__ __forceinline__ ull add2(ull a, ull b) {
    ull d; asm("add.rn.f32x2 %0, %1, %2;" : "=l"(d) : "l"(a), "l"(b)); return d;
}
__device__ __forceinline__ float2 unpack2(ull v) {
    float2 r; asm("mov.b64 {%0, %1}, %2;" : "=f"(r.x), "=f"(r.y) : "l"(v)); return r;
}
__device__ __forceinline__ unsigned cvtf16x2(float lo, float hi) {
    unsigned r; asm("cvt.rn.f16x2.f32 %0, %1, %2;" : "=r"(r) : "f"(hi), "f"(lo)); return r;
}
__device__ __forceinline__ ull h2f2(unsigned w) {
    ull d;
    asm("{ .reg .b16 l, h; .reg .f32 fl, fh;\n\t"
        "mov.b32 {l, h}, %1;\n\t"
        "cvt.f32.f16 fl, l;\n\t"
        "cvt.f32.f16 fh, h;\n\t"
        "mov.b64 %0, {fl, fh}; }"
        : "=l"(d) : "r"(w));
    return d;
}

__global__ void noop_kernel() {}

// pass1: hats[b,n,k,o] = sum_d x[b,n,d] W[n,k,d,o]; s0 += hats; store fp16.
// grid (148,2): x = n-chunk, y = b-half. 256 thr: warp w owns b-quad
// 32*half + 4w..+3; lane l: k = l&15, oh = l>>4.
__global__ void __launch_bounds__(256, 2)
pass1_kernel(const float* __restrict__ x, const float* __restrict__ W) {
    __shared__ __align__(16) float4 Wf4[2][544];          // 17 KB
    __shared__ __align__(16) float xs[CHUNK][8][32];      // 14 KB

    const int tid  = threadIdx.x;
    const int l    = tid & 31;
    const int w    = tid >> 5;
    const int k    = l & 15;
    const int oh   = l >> 4;
    const int half = blockIdx.y;
    const int bg0  = 32 * half + 4 * w;
    const int n0   = blockIdx.x * CHUNK;
    int nmax = 2048 - n0; if (nmax > CHUNK) nmax = CHUNK; if (nmax < 0) nmax = 0;

    for (int i = tid; i < nmax * 64; i += 256) {
        int ln = i >> 6, r = i & 63, bb = r >> 1, dq = r & 1;
        float4 v = *(const float4*)(x + ((size_t)(32 * half + bb) * 2048 + (size_t)(n0 + ln)) * 8 + dq * 4);
        xs[ln][dq * 4 + 0][bb] = v.x;
        xs[ln][dq * 4 + 1][bb] = v.y;
        xs[ln][dq * 4 + 2][bb] = v.z;
        xs[ln][dq * 4 + 3][bb] = v.w;
    }

    const int sD = (tid >> 2) & 7, sOq = tid & 3;
    const int sK0 = tid >> 5, sK1 = sK0 + 8;
    const int sdst0 = sD * 68 + sOq * 17 + sK0;
    const int sdst1 = sD * 68 + sOq * 17 + sK1;
    const float4* wsrc = (const float4*)(W + (size_t)n0 * 2048);
    float4 wr0 = make_float4(0.f, 0.f, 0.f, 0.f), wr1 = wr0;
    if (nmax > 0) { wr0 = wsrc[tid]; wr1 = wsrc[tid + 256]; }

    ull acc[4][4];
#pragma unroll
    for (int j = 0; j < 4; j++)
#pragma unroll
        for (int u = 0; u < 4; u++) acc[j][u] = 0ull;

    for (int ln = 0; ln < nmax; ln++) {
        Wf4[ln & 1][sdst0] = wr0;
        Wf4[ln & 1][sdst1] = wr1;
        if (ln + 1 < nmax) {
            const float4* ws = wsrc + (size_t)(ln + 1) * 512;
            wr0 = ws[tid]; wr1 = ws[tid + 256];
        }
        __syncthreads();

        const float4* wb = &Wf4[ln & 1][oh * 34 + k];

        ull h[4][4];
#pragma unroll
        for (int d = 0; d < 8; d++) {
            float4 xq = *(const float4*)&xs[ln][d][4 * w];
            ull xd[4];
            xd[0] = pack2(xq.x); xd[1] = pack2(xq.y);
            xd[2] = pack2(xq.z); xd[3] = pack2(xq.w);
            ulonglong2 wv0 = *(const ulonglong2*)&wb[d * 68];
            ulonglong2 wv1 = *(const ulonglong2*)&wb[d * 68 + 17];
#pragma unroll
            for (int j = 0; j < 4; j++) {
                if (d == 0) {
                    h[j][0] = mul2(xd[j], wv0.x);
                    h[j][1] = mul2(xd[j], wv0.y);
                    h[j][2] = mul2(xd[j], wv1.x);
                    h[j][3] = mul2(xd[j], wv1.y);
                } else {
                    h[j][0] = fma2(xd[j], wv0.x, h[j][0]);
                    h[j][1] = fma2(xd[j], wv0.y, h[j][1]);
                    h[j][2] = fma2(xd[j], wv1.x, h[j][2]);
                    h[j][3] = fma2(xd[j], wv1.y, h[j][3]);
                }
            }
        }

#pragma unroll
        for (int j = 0; j < 4; j++) {
            uint4 st;
            float2 a0 = unpack2(h[j][0]);
            float2 a1 = unpack2(h[j][1]);
            float2 a2 = unpack2(h[j][2]);
            float2 a3 = unpack2(h[j][3]);
            st.x = cvtf16x2(a0.x, a0.y);
            st.y = cvtf16x2(a1.x, a1.y);
            st.z = cvtf16x2(a2.x, a2.y);
            st.w = cvtf16x2(a3.x, a3.y);
            acc[j][0] = add2(acc[j][0], h[j][0]);
            acc[j][1] = add2(acc[j][1], h[j][1]);
            acc[j][2] = add2(acc[j][2], h[j][2]);
            acc[j][3] = add2(acc[j][3], h[j][3]);
            *(uint4*)(g_hats + ((size_t)(bg0 + j) * 2048 + (size_t)(n0 + ln)) * 256
                      + (size_t)k * 16 + 8 * oh) = st;
        }
    }

#pragma unroll
    for (int j = 0; j < 4; j++) {
        float* pp = g_part + ((size_t)blockIdx.x * 64 + (size_t)(bg0 + j)) * 256
                    + (size_t)k * 16 + 8 * oh;
        float2 v0 = unpack2(acc[j][0]);
        float2 v1 = unpack2(acc[j][1]);
        float2 v2 = unpack2(acc[j][2]);
        float2 v3 = unpack2(acc[j][3]);
        *(float4*)(pp)     = make_float4(v0.x, v0.y, v1.x, v1.y);
        *(float4*)(pp + 4) = make_float4(v2.x, v2.y, v3.x, v3.y);
    }
}

// route (R11 body, finer grid): grid 4096 = (b<64)*(g<64), 256 thr.
// Block handles 32 n; warp w handles n = g*32 + it*8 + w, 4 iterations.
// lane l: k = l&15, oh = l>>4 (8 o each). Sum-only softmax.
__global__ void __launch_bounds__(256) route_kernel() {
    const int b = blockIdx.x >> 6, g = blockIdx.x & 63;
    const int w = threadIdx.x >> 5, l = threadIdx.x & 31;
    const int k = l & 15, oh = l >> 4;

    ull rr[4];
    {
        const ull* rp = (const ull*)(g_route + ((size_t)b * 16 + k) * 16 + 8 * oh);
        rr[0] = rp[0]; rr[1] = rp[1]; rr[2] = rp[2]; rr[3] = rp[3];
    }

    ull acc[4] = {0ull, 0ull, 0ull, 0ull};
    const size_t lane_off = (size_t)k * 16 + 8 * oh;
    const unsigned short* hbase = g_hats + (size_t)b * 2048 * 256 + lane_off;

#pragma unroll
    for (int it = 0; it < 4; it++) {
        int n = g * 32 + it * 8 + w;
        uint4 v = *(const uint4*)(hbase + (size_t)n * 256);
        ull hh[4];
        hh[0] = h2f2(v.x); hh[1] = h2f2(v.y); hh[2] = h2f2(v.z); hh[3] = h2f2(v.w);

        ull t = mul2(hh[0], rr[0]);
        ull u = mul2(hh[1], rr[1]);
        t = fma2(hh[2], rr[2], t);
        u = fma2(hh[3], rr[3], u);
        float2 q = unpack2(add2(t, u));
        float pb = q.x + q.y;
        pb += __shfl_xor_sync(0xffffffffu, pb, 16);   // combine o-halves
        float e = __expf(pb);                         // |bias| small: no max-sub
        float s = e;
        s += __shfl_xor_sync(0xffffffffu, s, 1);
        s += __shfl_xor_sync(0xffffffffu, s, 2);
        s += __shfl_xor_sync(0xffffffffu, s, 4);
        s += __shfl_xor_sync(0xffffffffu, s, 8);
        ull c2 = pack2(__fdividef(e, s));
        acc[0] = fma2(c2, hh[0], acc[0]);
        acc[1] = fma2(c2, hh[1], acc[1]);
        acc[2] = fma2(c2, hh[2], acc[2]);
        acc[3] = fma2(c2, hh[3], acc[3]);
    }

    // cross-warp reduction via smem
    __shared__ float red[8][256];
    {
        float* dst = &red[w][k * 16 + 8 * oh];
        float2 v0 = unpack2(acc[0]);
        float2 v1 = unpack2(acc[1]);
        float2 v2 = unpack2(acc[2]);
        float2 v3 = unpack2(acc[3]);
        *(float4*)(dst)     = make_float4(v0.x, v0.y, v1.x, v1.y);
        *(float4*)(dst + 4) = make_float4(v2.x, v2.y, v3.x, v3.y);
    }
    __syncthreads();
    {
        const int t = threadIdx.x;
        float s = 0.f;
#pragma unroll
        for (int ww = 0; ww < 8; ww++) s += red[ww][t];
        g_part2[((size_t)g * 64 + b) * 256 + t] = s;
    }
}

// Reduce cnt chunks (g_part if src==0 else g_part2), squash, route/output.
// grid 64 (b), block 1024: q = tid>>8 (4-way split), t = tid&255 = k*16+o.
__global__ void __launch_bounds__(1024) squash_kernel(int src, int cnt, float scale,
                                                      int mode, float* __restrict__ out) {
    __shared__ float red[4][256];
    const int tid = threadIdx.x, q = tid >> 8, t = tid & 255;
    const int b = blockIdx.x;
    const float* base = (src == 0 ? g_part : g_part2) + (size_t)b * 256 + t;
    float s = 0.f;
#pragma unroll 4
    for (int j = q; j < cnt; j += 4)
        s += base[(size_t)j * 16384];
    red[q][t] = s;
    __syncthreads();
    if (tid < 256) {
        s = (red[0][t] + red[1][t]) + (red[2][t] + red[3][t]);
        s *= scale;
        float s2 = s * s;
        s2 += __shfl_xor_sync(0xffffffffu, s2, 1);
        s2 += __shfl_xor_sync(0xffffffffu, s2, 2);
        s2 += __shfl_xor_sync(0xffffffffu, s2, 4);
        s2 += __shfl_xor_sync(0xffffffffu, s2, 8);
        float sc = s2 / ((1.0f + s2) * sqrtf(s2));
        float v = sc * s;
        int idx = b * 256 + t;
        if (mode == 0)      g_route[idx] = v;    // route = out0
        else if (mode == 1) g_route[idx] += v;   // route = out0 + out1
        else                out[idx] = v;        // final [B,16,16]
    }
}

extern "C" void kernel_launch(void* const* d_in, const int* in_sizes, int n_in,
                              void* d_out, int out_size) {
    const float* x = (const float*)d_in[0];   // [64, 2048, 8]
    const float* W = (const float*)d_in[1];   // [2048, 16, 8, 16]
    float* out = (float*)d_out;               // [64, 16, 16]
    (void)in_sizes; (void)n_in; (void)out_size;

    noop_kernel<<<1, 1>>>();                                  // profiler alignment
    pass1_kernel<<<dim3(NBLK, 2), 256>>>(x, W);               // hats fp16 + s0 partials
    squash_kernel<<<64, 1024>>>(0, NBLK, 1.0f / 16.0f, 0, out); // out0 -> route
    route_kernel<<<4096, 256>>>();                            // 4th launch (profiled)
    squash_kernel<<<64, 1024>>>(1, GCH, 1.0f, 1, out);        // route += out1
    route_kernel<<<4096, 256>>>();                            // s2 partials
    squash_kernel<<<64, 1024>>>(1, GCH, 1.0f, 2, out);        // final output
}

// round 14
// speedup vs baseline: 1.1465x; 1.1465x over previous
#include <cuda_runtime.h>

// CapsuleBlock: B=64, N=2048, D_in=8, K=16, O=16, 3 routing iters.
// R14: exact R11 structure (best, 68.4us) + L2 residency management:
// hats stored/loaded with L2::evict_last (67MB fits the 126MB L2),
// W streamed with L2::evict_first so it can't evict hats. Routes should
// hit L2 (~6.9TB/s, 234cyc) instead of DRAM (40% util, 577cyc).

#define NBLK  148
#define CHUNK 14           // 148*14 = 2072 >= 2048

__device__ float g_part [(size_t)NBLK * 16384];  // pass1 partials [blk][b][k][o]
__device__ float g_part2[(size_t)16 * 16384];    // route partials [g][b][k][o]
__device__ float g_route[16384];                 // routing vector [b][k][o]
__device__ __align__(16) unsigned short g_hats[(size_t)64 * 2048 * 256]; // fp16 [b][n][k][o]

typedef unsigned long long ull;

__device__ __forceinline__ ull pack2(float v) {
    ull r; asm("mov.b64 %0, {%1, %1};" : "=l"(r) : "f"(v)); return r;
}
__device__ __forceinline__ ull fma2(ull a, ull b, ull c) {
    ull d; asm("fma.rn.f32x2 %0, %1, %2, %3;" : "=l"(d) : "l"(a), "l"(b), "l"(c)); return d;
}
__device__ __forceinline__ ull mul2(ull a, ull b) {
    ull d; asm("mul.rn.f32x2 %0, %1, %2;" : "=l"(d) : "l"(a), "l"(b)); return d;
}
__device__ __forceinline__ ull add2(ull a, ull b) {
    ull d; asm("add.rn.f32x2 %0, %1, %2;" : "=l"(d) : "l"(a), "l"(b)); return d;
}
__device__ __forceinline__ float2 unpack2(ull v) {
    float2 r; asm("mov.b64 {%0, %1}, %2;" : "=f"(r.x), "=f"(r.y) : "l"(v)); return r;
}
__device__ __forceinline__ unsigned cvtf16x2(float lo, float hi) {
    unsigned r; asm("cvt.rn.f16x2.f32 %0, %1, %2;" : "=r"(r) : "f"(hi), "f"(lo)); return r;
}
__device__ __forceinline__ ull h2f2(unsigned w) {
    ull d;
    asm("{ .reg .b16 l, h; .reg .f32 fl, fh;\n\t"
        "mov.b32 {l, h}, %1;\n\t"
        "cvt.f32.f16 fl, l;\n\t"
        "cvt.f32.f16 fh, h;\n\t"
        "mov.b64 %0, {fl, fh}; }"
        : "=l"(d) : "r"(w));
    return d;
}

// L2 eviction policies (sm_80+)
__device__ __forceinline__ ull pol_evict_last() {
    ull p; asm("createpolicy.fractional.L2::evict_last.b64 %0, 1.0;" : "=l"(p)); return p;
}
__device__ __forceinline__ ull pol_evict_first() {
    ull p; asm("createpolicy.fractional.L2::evict_first.b64 %0, 1.0;" : "=l"(p)); return p;
}
__device__ __forceinline__ void st_hats(void* p, uint4 v, ull pol) {
    asm volatile("st.global.L2::cache_hint.v4.u32 [%0], {%1, %2, %3, %4}, %5;"
                 :: "l"(p), "r"(v.x), "r"(v.y), "r"(v.z), "r"(v.w), "l"(pol) : "memory");
}
__device__ __forceinline__ uint4 ld_hats(const void* p, ull pol) {
    uint4 v;
    asm("ld.global.nc.L2::cache_hint.v4.u32 {%0, %1, %2, %3}, [%4], %5;"
        : "=r"(v.x), "=r"(v.y), "=r"(v.z), "=r"(v.w) : "l"(p), "l"(pol));
    return v;
}
__device__ __forceinline__ float4 ld_stream_f4(const void* p, ull pol) {
    float4 v;
    asm("ld.global.nc.L2::cache_hint.v4.f32 {%0, %1, %2, %3}, [%4], %5;"
        : "=f"(v.x), "=f"(v.y), "=f"(v.z), "=f"(v.w) : "l"(p), "l"(pol));
    return v;
}

__global__ void noop_kernel() {}

// pass1: hats[b,n,k,o] = sum_d x[b,n,d] W[n,k,d,o]; s0 += hats; store fp16
// with L2 evict_last. W streamed with evict_first. grid (148,2).
__global__ void __launch_bounds__(256, 2)
pass1_kernel(const float* __restrict__ x, const float* __restrict__ W) {
    __shared__ __align__(16) float4 Wf4[2][544];          // 17 KB
    __shared__ __align__(16) float xs[CHUNK][8][32];      // 14 KB

    const int tid  = threadIdx.x;
    const int l    = tid & 31;
    const int w    = tid >> 5;
    const int k    = l & 15;
    const int oh   = l >> 4;
    const int half = blockIdx.y;
    const int bg0  = 32 * half + 4 * w;
    const int n0   = blockIdx.x * CHUNK;
    int nmax = 2048 - n0; if (nmax > CHUNK) nmax = CHUNK; if (nmax < 0) nmax = 0;

    const ull pl_last  = pol_evict_last();
    const ull pl_first = pol_evict_first();

    for (int i = tid; i < nmax * 64; i += 256) {
        int ln = i >> 6, r = i & 63, bb = r >> 1, dq = r & 1;
        float4 v = *(const float4*)(x + ((size_t)(32 * half + bb) * 2048 + (size_t)(n0 + ln)) * 8 + dq * 4);
        xs[ln][dq * 4 + 0][bb] = v.x;
        xs[ln][dq * 4 + 1][bb] = v.y;
        xs[ln][dq * 4 + 2][bb] = v.z;
        xs[ln][dq * 4 + 3][bb] = v.w;
    }

    const int sD = (tid >> 2) & 7, sOq = tid & 3;
    const int sK0 = tid >> 5, sK1 = sK0 + 8;
    const int sdst0 = sD * 68 + sOq * 17 + sK0;
    const int sdst1 = sD * 68 + sOq * 17 + sK1;
    const float4* wsrc = (const float4*)(W + (size_t)n0 * 2048);
    float4 wr0 = make_float4(0.f, 0.f, 0.f, 0.f), wr1 = wr0;
    if (nmax > 0) {
        wr0 = ld_stream_f4(wsrc + tid, pl_first);
        wr1 = ld_stream_f4(wsrc + tid + 256, pl_first);
    }

    ull acc[4][4];
#pragma unroll
    for (int j = 0; j < 4; j++)
#pragma unroll
        for (int u = 0; u < 4; u++) acc[j][u] = 0ull;

    for (int ln = 0; ln < nmax; ln++) {
        Wf4[ln & 1][sdst0] = wr0;
        Wf4[ln & 1][sdst1] = wr1;
        if (ln + 1 < nmax) {
            const float4* ws = wsrc + (size_t)(ln + 1) * 512;
            wr0 = ld_stream_f4(ws + tid, pl_first);
            wr1 = ld_stream_f4(ws + tid + 256, pl_first);
        }
        __syncthreads();

        const float4* wb = &Wf4[ln & 1][oh * 34 + k];

        ull h[4][4];
#pragma unroll
        for (int d = 0; d < 8; d++) {
            float4 xq = *(const float4*)&xs[ln][d][4 * w];
            ull xd[4];
            xd[0] = pack2(xq.x); xd[1] = pack2(xq.y);
            xd[2] = pack2(xq.z); xd[3] = pack2(xq.w);
            ulonglong2 wv0 = *(const ulonglong2*)&wb[d * 68];
            ulonglong2 wv1 = *(const ulonglong2*)&wb[d * 68 + 17];
#pragma unroll
            for (int j = 0; j < 4; j++) {
                if (d == 0) {
                    h[j][0] = mul2(xd[j], wv0.x);
                    h[j][1] = mul2(xd[j], wv0.y);
                    h[j][2] = mul2(xd[j], wv1.x);
                    h[j][3] = mul2(xd[j], wv1.y);
                } else {
                    h[j][0] = fma2(xd[j], wv0.x, h[j][0]);
                    h[j][1] = fma2(xd[j], wv0.y, h[j][1]);
                    h[j][2] = fma2(xd[j], wv1.x, h[j][2]);
                    h[j][3] = fma2(xd[j], wv1.y, h[j][3]);
                }
            }
        }

#pragma unroll
        for (int j = 0; j < 4; j++) {
            uint4 st;
            float2 a0 = unpack2(h[j][0]);
            float2 a1 = unpack2(h[j][1]);
            float2 a2 = unpack2(h[j][2]);
            float2 a3 = unpack2(h[j][3]);
            st.x = cvtf16x2(a0.x, a0.y);
            st.y = cvtf16x2(a1.x, a1.y);
            st.z = cvtf16x2(a2.x, a2.y);
            st.w = cvtf16x2(a3.x, a3.y);
            acc[j][0] = add2(acc[j][0], h[j][0]);
            acc[j][1] = add2(acc[j][1], h[j][1]);
            acc[j][2] = add2(acc[j][2], h[j][2]);
            acc[j][3] = add2(acc[j][3], h[j][3]);
            st_hats(g_hats + ((size_t)(bg0 + j) * 2048 + (size_t)(n0 + ln)) * 256
                    + (size_t)k * 16 + 8 * oh, st, pl_last);
        }
    }

#pragma unroll
    for (int j = 0; j < 4; j++) {
        float* pp = g_part + ((size_t)blockIdx.x * 64 + (size_t)(bg0 + j)) * 256
                    + (size_t)k * 16 + 8 * oh;
        float2 v0 = unpack2(acc[j][0]);
        float2 v1 = unpack2(acc[j][1]);
        float2 v2 = unpack2(acc[j][2]);
        float2 v3 = unpack2(acc[j][3]);
        *(float4*)(pp)     = make_float4(v0.x, v0.y, v1.x, v1.y);
        *(float4*)(pp + 4) = make_float4(v2.x, v2.y, v3.x, v3.y);
    }
}

// route (R11 body): grid 1024 = (b<64)*(g<16), 256 thr.
// Warp w handles n = g*128 + it*8 + w; lane l: k=l&15, oh=l>>4 (8 o each).
// hats loads with L2 evict_last (stay resident for 2nd route pass).
__global__ void __launch_bounds__(256) route_kernel() {
    const int b = blockIdx.x >> 4, g = blockIdx.x & 15;
    const int w = threadIdx.x >> 5, l = threadIdx.x & 31;
    const int k = l & 15, oh = l >> 4;

    const ull pl_last = pol_evict_last();

    ull rr[4];
    {
        const ull* rp = (const ull*)(g_route + ((size_t)b * 16 + k) * 16 + 8 * oh);
        rr[0] = rp[0]; rr[1] = rp[1]; rr[2] = rp[2]; rr[3] = rp[3];
    }

    ull acc[4] = {0ull, 0ull, 0ull, 0ull};
    const size_t lane_off = (size_t)k * 16 + 8 * oh;
    const unsigned short* hbase = g_hats + (size_t)b * 2048 * 256 + lane_off;

#pragma unroll 4
    for (int it = 0; it < 16; it++) {
        int n = g * 128 + it * 8 + w;
        uint4 v = ld_hats(hbase + (size_t)n * 256, pl_last);
        ull hh[4];
        hh[0] = h2f2(v.x); hh[1] = h2f2(v.y); hh[2] = h2f2(v.z); hh[3] = h2f2(v.w);

        ull t = mul2(hh[0], rr[0]);
        ull u = mul2(hh[1], rr[1]);
        t = fma2(hh[2], rr[2], t);
        u = fma2(hh[3], rr[3], u);
        float2 q = unpack2(add2(t, u));
        float pb = q.x + q.y;
        pb += __shfl_xor_sync(0xffffffffu, pb, 16);   // combine o-halves
        float e = __expf(pb);                         // |bias| small: no max-sub
        float s = e;
        s += __shfl_xor_sync(0xffffffffu, s, 1);
        s += __shfl_xor_sync(0xffffffffu, s, 2);
        s += __shfl_xor_sync(0xffffffffu, s, 4);
        s += __shfl_xor_sync(0xffffffffu, s, 8);
        ull c2 = pack2(__fdividef(e, s));
        acc[0] = fma2(c2, hh[0], acc[0]);
        acc[1] = fma2(c2, hh[1], acc[1]);
        acc[2] = fma2(c2, hh[2], acc[2]);
        acc[3] = fma2(c2, hh[3], acc[3]);
    }

    // cross-warp reduction via smem
    __shared__ float red[8][256];
    {
        float* dst = &red[w][k * 16 + 8 * oh];
        float2 v0 = unpack2(acc[0]);
        float2 v1 = unpack2(acc[1]);
        float2 v2 = unpack2(acc[2]);
        float2 v3 = unpack2(acc[3]);
        *(float4*)(dst)     = make_float4(v0.x, v0.y, v1.x, v1.y);
        *(float4*)(dst + 4) = make_float4(v2.x, v2.y, v3.x, v3.y);
    }
    __syncthreads();
    {
        const int t = threadIdx.x;
        float s = 0.f;
#pragma unroll
        for (int ww = 0; ww < 8; ww++) s += red[ww][t];
        g_part2[((size_t)g * 64 + b) * 256 + t] = s;
    }
}

// Reduce cnt chunks (g_part if src==0 else g_part2), squash, route/output.
__global__ void __launch_bounds__(1024) squash_kernel(int src, int cnt, float scale,
                                                      int mode, float* __restrict__ out) {
    __shared__ float red[4][256];
    const int tid = threadIdx.x, q = tid >> 8, t = tid & 255;
    const int b = blockIdx.x;
    const float* base = (src == 0 ? g_part : g_part2) + (size_t)b * 256 + t;
    float s = 0.f;
#pragma unroll 4
    for (int j = q; j < cnt; j += 4)
        s += base[(size_t)j * 16384];
    red[q][t] = s;
    __syncthreads();
    if (tid < 256) {
        s = (red[0][t] + red[1][t]) + (red[2][t] + red[3][t]);
        s *= scale;
        float s2 = s * s;
        s2 += __shfl_xor_sync(0xffffffffu, s2, 1);
        s2 += __shfl_xor_sync(0xffffffffu, s2, 2);
        s2 += __shfl_xor_sync(0xffffffffu, s2, 4);
        s2 += __shfl_xor_sync(0xffffffffu, s2, 8);
        float sc = s2 / ((1.0f + s2) * sqrtf(s2));
        float v = sc * s;
        int idx = b * 256 + t;
        if (mode == 0)      g_route[idx] = v;    // route = out0
        else if (mode == 1) g_route[idx] += v;   // route = out0 + out1
        else                out[idx] = v;        // final [B,16,16]
    }
}

extern "C" void kernel_launch(void* const* d_in, const int* in_sizes, int n_in,
                              void* d_out, int out_size) {
    const float* x = (const float*)d_in[0];   // [64, 2048, 8]
    const float* W = (const float*)d_in[1];   // [2048, 16, 8, 16]
    float* out = (float*)d_out;               // [64, 16, 16]
    (void)in_sizes; (void)n_in; (void)out_size;

    noop_kernel<<<1, 1>>>();                                  // profiler alignment
    pass1_kernel<<<dim3(NBLK, 2), 256>>>(x, W);               // hats fp16 + s0 partials
    squash_kernel<<<64, 1024>>>(0, NBLK, 1.0f / 16.0f, 0, out); // out0 -> route
    route_kernel<<<1024, 256>>>();                            // 4th launch (profiled)
    squash_kernel<<<64, 1024>>>(1, 16, 1.0f, 1, out);         // route += out1
    route_kernel<<<1024, 256>>>();                            // s2 partials
    squash_kernel<<<64, 1024>>>(1, 16, 1.0f, 2, out);         // final output
}

// round 15
// speedup vs baseline: 1.2504x; 1.0906x over previous
#include <cuda_runtime.h>

// CapsuleBlock: B=64, N=2048, D_in=8, K=16, O=16, 3 routing iters.
// R15: route rebuilt around cp.async (LDGSTS) smem pipeline — load depth is
// bounded by smem (4x8KB ring, depth 3), not registers, so DRAM stays full.
// pass1/squash = exact R11 (best). Route math unchanged (sum-only softmax).

#define NBLK  148
#define CHUNK 14           // 148*14 = 2072 >= 2048

__device__ float g_part [(size_t)NBLK * 16384];  // pass1 partials [blk][b][k][o]
__device__ float g_part2[(size_t)16 * 16384];    // route partials [g][b][k][o]
__device__ float g_route[16384];                 // routing vector [b][k][o]
__device__ __align__(16) unsigned short g_hats[(size_t)64 * 2048 * 256]; // fp16 [b][n][k][o]

typedef unsigned long long ull;

__device__ __forceinline__ ull pack2(float v) {
    ull r; asm("mov.b64 %0, {%1, %1};" : "=l"(r) : "f"(v)); return r;
}
__device__ __forceinline__ ull fma2(ull a, ull b, ull c) {
    ull d; asm("fma.rn.f32x2 %0, %1, %2, %3;" : "=l"(d) : "l"(a), "l"(b), "l"(c)); return d;
}
__device__ __forceinline__ ull mul2(ull a, ull b) {
    ull d; asm("mul.rn.f32x2 %0, %1, %2;" : "=l"(d) : "l"(a), "l"(b)); return d;
}
__device__ __forceinline__ ull add2(ull a, ull b) {
    ull d; asm("add.rn.f32x2 %0, %1, %2;" : "=l"(d) : "l"(a), "l"(b)); return d;
}
__device__ __forceinline__ float2 unpack2(ull v) {
    float2 r; asm("mov.b64 {%0, %1}, %2;" : "=f"(r.x), "=f"(r.y) : "l"(v)); return r;
}
__device__ __forceinline__ unsigned cvtf16x2(float lo, float hi) {
    unsigned r; asm("cvt.rn.f16x2.f32 %0, %1, %2;" : "=r"(r) : "f"(hi), "f"(lo)); return r;
}
__device__ __forceinline__ ull h2f2(unsigned w) {
    ull d;
    asm("{ .reg .b16 l, h; .reg .f32 fl, fh;\n\t"
        "mov.b32 {l, h}, %1;\n\t"
        "cvt.f32.f16 fl, l;\n\t"
        "cvt.f32.f16 fh, h;\n\t"
        "mov.b64 %0, {fl, fh}; }"
        : "=l"(d) : "r"(w));
    return d;
}
__device__ __forceinline__ void cp16(unsigned smem_dst, const void* gsrc) {
    asm volatile("cp.async.cg.shared.global [%0], [%1], 16;"
                 :: "r"(smem_dst), "l"(gsrc) : "memory");
}
__device__ __forceinline__ void cp_commit() {
    asm volatile("cp.async.commit_group;" ::: "memory");
}
__device__ __forceinline__ void cp_wait(int wg) {
    switch (wg) {
        case 0: asm volatile("cp.async.wait_group 0;" ::: "memory"); break;
        case 1: asm volatile("cp.async.wait_group 1;" ::: "memory"); break;
        default: asm volatile("cp.async.wait_group 2;" ::: "memory"); break;
    }
}

__global__ void noop_kernel() {}

// pass1 (R11): hats = sum_d x*W; s0 += hats; store fp16. grid (148,2).
__global__ void __launch_bounds__(256, 2)
pass1_kernel(const float* __restrict__ x, const float* __restrict__ W) {
    __shared__ __align__(16) float4 Wf4[2][544];          // 17 KB
    __shared__ __align__(16) float xs[CHUNK][8][32];      // 14 KB

    const int tid  = threadIdx.x;
    const int l    = tid & 31;
    const int w    = tid >> 5;
    const int k    = l & 15;
    const int oh   = l >> 4;
    const int half = blockIdx.y;
    const int bg0  = 32 * half + 4 * w;
    const int n0   = blockIdx.x * CHUNK;
    int nmax = 2048 - n0; if (nmax > CHUNK) nmax = CHUNK; if (nmax < 0) nmax = 0;

    for (int i = tid; i < nmax * 64; i += 256) {
        int ln = i >> 6, r = i & 63, bb = r >> 1, dq = r & 1;
        float4 v = *(const float4*)(x + ((size_t)(32 * half + bb) * 2048 + (size_t)(n0 + ln)) * 8 + dq * 4);
        xs[ln][dq * 4 + 0][bb] = v.x;
        xs[ln][dq * 4 + 1][bb] = v.y;
        xs[ln][dq * 4 + 2][bb] = v.z;
        xs[ln][dq * 4 + 3][bb] = v.w;
    }

    const int sD = (tid >> 2) & 7, sOq = tid & 3;
    const int sK0 = tid >> 5, sK1 = sK0 + 8;
    const int sdst0 = sD * 68 + sOq * 17 + sK0;
    const int sdst1 = sD * 68 + sOq * 17 + sK1;
    const float4* wsrc = (const float4*)(W + (size_t)n0 * 2048);
    float4 wr0 = make_float4(0.f, 0.f, 0.f, 0.f), wr1 = wr0;
    if (nmax > 0) { wr0 = wsrc[tid]; wr1 = wsrc[tid + 256]; }

    ull acc[4][4];
#pragma unroll
    for (int j = 0; j < 4; j++)
#pragma unroll
        for (int u = 0; u < 4; u++) acc[j][u] = 0ull;

    for (int ln = 0; ln < nmax; ln++) {
        Wf4[ln & 1][sdst0] = wr0;
        Wf4[ln & 1][sdst1] = wr1;
        if (ln + 1 < nmax) {
            const float4* ws = wsrc + (size_t)(ln + 1) * 512;
            wr0 = ws[tid]; wr1 = ws[tid + 256];
        }
        __syncthreads();

        const float4* wb = &Wf4[ln & 1][oh * 34 + k];

        ull h[4][4];
#pragma unroll
        for (int d = 0; d < 8; d++) {
            float4 xq = *(const float4*)&xs[ln][d][4 * w];
            ull xd[4];
            xd[0] = pack2(xq.x); xd[1] = pack2(xq.y);
            xd[2] = pack2(xq.z); xd[3] = pack2(xq.w);
            ulonglong2 wv0 = *(const ulonglong2*)&wb[d * 68];
            ulonglong2 wv1 = *(const ulonglong2*)&wb[d * 68 + 17];
#pragma unroll
            for (int j = 0; j < 4; j++) {
                if (d == 0) {
                    h[j][0] = mul2(xd[j], wv0.x);
                    h[j][1] = mul2(xd[j], wv0.y);
                    h[j][2] = mul2(xd[j], wv1.x);
                    h[j][3] = mul2(xd[j], wv1.y);
                } else {
                    h[j][0] = fma2(xd[j], wv0.x, h[j][0]);
                    h[j][1] = fma2(xd[j], wv0.y, h[j][1]);
                    h[j][2] = fma2(xd[j], wv1.x, h[j][2]);
                    h[j][3] = fma2(xd[j], wv1.y, h[j][3]);
                }
            }
        }

#pragma unroll
        for (int j = 0; j < 4; j++) {
            uint4 st;
            float2 a0 = unpack2(h[j][0]);
            float2 a1 = unpack2(h[j][1]);
            float2 a2 = unpack2(h[j][2]);
            float2 a3 = unpack2(h[j][3]);
            st.x = cvtf16x2(a0.x, a0.y);
            st.y = cvtf16x2(a1.x, a1.y);
            st.z = cvtf16x2(a2.x, a2.y);
            st.w = cvtf16x2(a3.x, a3.y);
            acc[j][0] = add2(acc[j][0], h[j][0]);
            acc[j][1] = add2(acc[j][1], h[j][1]);
            acc[j][2] = add2(acc[j][2], h[j][2]);
            acc[j][3] = add2(acc[j][3], h[j][3]);
            *(uint4*)(g_hats + ((size_t)(bg0 + j) * 2048 + (size_t)(n0 + ln)) * 256
                      + (size_t)k * 16 + 8 * oh) = st;
        }
    }

#pragma unroll
    for (int j = 0; j < 4; j++) {
        float* pp = g_part + ((size_t)blockIdx.x * 64 + (size_t)(bg0 + j)) * 256
                    + (size_t)k * 16 + 8 * oh;
        float2 v0 = unpack2(acc[j][0]);
        float2 v1 = unpack2(acc[j][1]);
        float2 v2 = unpack2(acc[j][2]);
        float2 v3 = unpack2(acc[j][3]);
        *(float4*)(pp)     = make_float4(v0.x, v0.y, v1.x, v1.y);
        *(float4*)(pp + 4) = make_float4(v2.x, v2.y, v3.x, v3.y);
    }
}

// route v3: grid 1024 = (b<64)*(g<16), 256 thr. Block streams its 64KB hats
// slice through a 4x8KB cp.async ring (depth 3). Chunk = 16 n; warp computes
// 2 n per chunk from smem. Softmax math unchanged from R11.
__global__ void __launch_bounds__(256) route_kernel() {
    __shared__ __align__(16) unsigned char hbuf[4][8192];  // 32 KB ring
    __shared__ float red[8][256];                          // 8 KB

    const int b = blockIdx.x >> 4, g = blockIdx.x & 15;
    const int w = threadIdx.x >> 5, l = threadIdx.x & 31;
    const int k = l & 15, oh = l >> 4;

    const unsigned char* gsrc = (const unsigned char*)g_hats
        + ((size_t)b * 2048 + (size_t)g * 128) * 512;      // contiguous 64 KB
    const unsigned sbase = (unsigned)__cvta_generic_to_shared(hbuf);
    const int t16 = threadIdx.x * 16;

    // prologue: issue chunks 0..2
#pragma unroll
    for (int c = 0; c < 3; c++) {
        unsigned d = sbase + c * 8192 + t16;
        const unsigned char* s = gsrc + c * 8192 + t16;
        cp16(d, s);
        cp16(d + 4096, s + 4096);
        cp_commit();
    }

    ull rr[4];
    {
        const ull* rp = (const ull*)(g_route + ((size_t)b * 16 + k) * 16 + 8 * oh);
        rr[0] = rp[0]; rr[1] = rp[1]; rr[2] = rp[2]; rr[3] = rp[3];
    }

    ull acc[4] = {0ull, 0ull, 0ull, 0ull};
    const int loff = k * 32 + oh * 16;                     // byte offset in a 512B row

#pragma unroll
    for (int c = 0; c < 8; c++) {
        int wg = 7 - c; if (wg > 2) wg = 2;
        cp_wait(wg);
        __syncthreads();                                   // chunk c visible to all
        if (c + 3 < 8) {
            unsigned d = sbase + ((c + 3) & 3) * 8192 + t16;
            const unsigned char* s = gsrc + (size_t)(c + 3) * 8192 + t16;
            cp16(d, s);
            cp16(d + 4096, s + 4096);
            cp_commit();
        }
        const unsigned char* buf = hbuf[c & 3];
#pragma unroll
        for (int it = 0; it < 2; it++) {
            int nl = it * 8 + w;
            uint4 v = *(const uint4*)(buf + nl * 512 + loff);
            ull hh[4];
            hh[0] = h2f2(v.x); hh[1] = h2f2(v.y); hh[2] = h2f2(v.z); hh[3] = h2f2(v.w);

            ull t = mul2(hh[0], rr[0]);
            ull u = mul2(hh[1], rr[1]);
            t = fma2(hh[2], rr[2], t);
            u = fma2(hh[3], rr[3], u);
            float2 q = unpack2(add2(t, u));
            float pb = q.x + q.y;
            pb += __shfl_xor_sync(0xffffffffu, pb, 16);    // combine o-halves
            float e = __expf(pb);                          // |bias| small: no max-sub
            float s = e;
            s += __shfl_xor_sync(0xffffffffu, s, 1);
            s += __shfl_xor_sync(0xffffffffu, s, 2);
            s += __shfl_xor_sync(0xffffffffu, s, 4);
            s += __shfl_xor_sync(0xffffffffu, s, 8);
            ull c2 = pack2(__fdividef(e, s));
            acc[0] = fma2(c2, hh[0], acc[0]);
            acc[1] = fma2(c2, hh[1], acc[1]);
            acc[2] = fma2(c2, hh[2], acc[2]);
            acc[3] = fma2(c2, hh[3], acc[3]);
        }
        __syncthreads();                                   // buffer free for reuse
    }

    // cross-warp reduction via smem
    {
        float* dst = &red[w][k * 16 + 8 * oh];
        float2 v0 = unpack2(acc[0]);
        float2 v1 = unpack2(acc[1]);
        float2 v2 = unpack2(acc[2]);
        float2 v3 = unpack2(acc[3]);
        *(float4*)(dst)     = make_float4(v0.x, v0.y, v1.x, v1.y);
        *(float4*)(dst + 4) = make_float4(v2.x, v2.y, v3.x, v3.y);
    }
    __syncthreads();
    {
        const int t = threadIdx.x;
        float s = 0.f;
#pragma unroll
        for (int ww = 0; ww < 8; ww++) s += red[ww][t];
        g_part2[((size_t)g * 64 + b) * 256 + t] = s;
    }
}

// Reduce cnt chunks (g_part if src==0 else g_part2), squash, route/output.
__global__ void __launch_bounds__(1024) squash_kernel(int src, int cnt, float scale,
                                                      int mode, float* __restrict__ out) {
    __shared__ float red[4][256];
    const int tid = threadIdx.x, q = tid >> 8, t = tid & 255;
    const int b = blockIdx.x;
    const float* base = (src == 0 ? g_part : g_part2) + (size_t)b * 256 + t;
    float s = 0.f;
#pragma unroll 4
    for (int j = q; j < cnt; j += 4)
        s += base[(size_t)j * 16384];
    red[q][t] = s;
    __syncthreads();
    if (tid < 256) {
        s = (red[0][t] + red[1][t]) + (red[2][t] + red[3][t]);
        s *= scale;
        float s2 = s * s;
        s2 += __shfl_xor_sync(0xffffffffu, s2, 1);
        s2 += __shfl_xor_sync(0xffffffffu, s2, 2);
        s2 += __shfl_xor_sync(0xffffffffu, s2, 4);
        s2 += __shfl_xor_sync(0xffffffffu, s2, 8);
        float sc = s2 / ((1.0f + s2) * sqrtf(s2));
        float v = sc * s;
        int idx = b * 256 + t;
        if (mode == 0)      g_route[idx] = v;    // route = out0
        else if (mode == 1) g_route[idx] += v;   // route = out0 + out1
        else                out[idx] = v;        // final [B,16,16]
    }
}

extern "C" void kernel_launch(void* const* d_in, const int* in_sizes, int n_in,
                              void* d_out, int out_size) {
    const float* x = (const float*)d_in[0];   // [64, 2048, 8]
    const float* W = (const float*)d_in[1];   // [2048, 16, 8, 16]
    float* out = (float*)d_out;               // [64, 16, 16]
    (void)in_sizes; (void)n_in; (void)out_size;

    noop_kernel<<<1, 1>>>();                                  // profiler alignment
    pass1_kernel<<<dim3(NBLK, 2), 256>>>(x, W);               // hats fp16 + s0 partials
    squash_kernel<<<64, 1024>>>(0, NBLK, 1.0f / 16.0f, 0, out); // out0 -> route
    route_kernel<<<1024, 256>>>();                            // 4th launch (profiled)
    squash_kernel<<<64, 1024>>>(1, 16, 1.0f, 1, out);         // route += out1
    route_kernel<<<1024, 256>>>();                            // s2 partials
    squash_kernel<<<64, 1024>>>(1, 16, 1.0f, 2, out);         // final output
}

// round 16
// speedup vs baseline: 1.2982x; 1.0382x over previous
#include <cuda_runtime.h>

// CapsuleBlock: B=64, N=2048, D_in=8, K=16, O=16, 3 routing iters.
// R16: route v4 — warp-private cp.async pipelines (4x1KB ring per warp,
// depth 3, __syncwarp only; ZERO block barriers in the stream loop).
// pass1/squash unchanged from R15 (= R11 form).

#define NBLK  148
#define CHUNK 14           // 148*14 = 2072 >= 2048

__device__ float g_part [(size_t)NBLK * 16384];  // pass1 partials [blk][b][k][o]
__device__ float g_part2[(size_t)16 * 16384];    // route partials [g][b][k][o]
__device__ float g_route[16384];                 // routing vector [b][k][o]
__device__ __align__(16) unsigned short g_hats[(size_t)64 * 2048 * 256]; // fp16 [b][n][k][o]

typedef unsigned long long ull;

__device__ __forceinline__ ull pack2(float v) {
    ull r; asm("mov.b64 %0, {%1, %1};" : "=l"(r) : "f"(v)); return r;
}
__device__ __forceinline__ ull fma2(ull a, ull b, ull c) {
    ull d; asm("fma.rn.f32x2 %0, %1, %2, %3;" : "=l"(d) : "l"(a), "l"(b), "l"(c)); return d;
}
__device__ __forceinline__ ull mul2(ull a, ull b) {
    ull d; asm("mul.rn.f32x2 %0, %1, %2;" : "=l"(d) : "l"(a), "l"(b)); return d;
}
__device__ __forceinline__ ull add2(ull a, ull b) {
    ull d; asm("add.rn.f32x2 %0, %1, %2;" : "=l"(d) : "l"(a), "l"(b)); return d;
}
__device__ __forceinline__ float2 unpack2(ull v) {
    float2 r; asm("mov.b64 {%0, %1}, %2;" : "=f"(r.x), "=f"(r.y) : "l"(v)); return r;
}
__device__ __forceinline__ unsigned cvtf16x2(float lo, float hi) {
    unsigned r; asm("cvt.rn.f16x2.f32 %0, %1, %2;" : "=r"(r) : "f"(hi), "f"(lo)); return r;
}
__device__ __forceinline__ ull h2f2(unsigned w) {
    ull d;
    asm("{ .reg .b16 l, h; .reg .f32 fl, fh;\n\t"
        "mov.b32 {l, h}, %1;\n\t"
        "cvt.f32.f16 fl, l;\n\t"
        "cvt.f32.f16 fh, h;\n\t"
        "mov.b64 %0, {fl, fh}; }"
        : "=l"(d) : "r"(w));
    return d;
}
__device__ __forceinline__ void cp16(unsigned smem_dst, const void* gsrc) {
    asm volatile("cp.async.cg.shared.global [%0], [%1], 16;"
                 :: "r"(smem_dst), "l"(gsrc) : "memory");
}
__device__ __forceinline__ void cp_commit() {
    asm volatile("cp.async.commit_group;" ::: "memory");
}
__device__ __forceinline__ void cp_wait(int wg) {
    switch (wg) {
        case 0: asm volatile("cp.async.wait_group 0;" ::: "memory"); break;
        case 1: asm volatile("cp.async.wait_group 1;" ::: "memory"); break;
        default: asm volatile("cp.async.wait_group 2;" ::: "memory"); break;
    }
}

__global__ void noop_kernel() {}

// pass1 (R11): hats = sum_d x*W; s0 += hats; store fp16. grid (148,2).
__global__ void __launch_bounds__(256, 2)
pass1_kernel(const float* __restrict__ x, const float* __restrict__ W) {
    __shared__ __align__(16) float4 Wf4[2][544];          // 17 KB
    __shared__ __align__(16) float xs[CHUNK][8][32];      // 14 KB

    const int tid  = threadIdx.x;
    const int l    = tid & 31;
    const int w    = tid >> 5;
    const int k    = l & 15;
    const int oh   = l >> 4;
    const int half = blockIdx.y;
    const int bg0  = 32 * half + 4 * w;
    const int n0   = blockIdx.x * CHUNK;
    int nmax = 2048 - n0; if (nmax > CHUNK) nmax = CHUNK; if (nmax < 0) nmax = 0;

    for (int i = tid; i < nmax * 64; i += 256) {
        int ln = i >> 6, r = i & 63, bb = r >> 1, dq = r & 1;
        float4 v = *(const float4*)(x + ((size_t)(32 * half + bb) * 2048 + (size_t)(n0 + ln)) * 8 + dq * 4);
        xs[ln][dq * 4 + 0][bb] = v.x;
        xs[ln][dq * 4 + 1][bb] = v.y;
        xs[ln][dq * 4 + 2][bb] = v.z;
        xs[ln][dq * 4 + 3][bb] = v.w;
    }

    const int sD = (tid >> 2) & 7, sOq = tid & 3;
    const int sK0 = tid >> 5, sK1 = sK0 + 8;
    const int sdst0 = sD * 68 + sOq * 17 + sK0;
    const int sdst1 = sD * 68 + sOq * 17 + sK1;
    const float4* wsrc = (const float4*)(W + (size_t)n0 * 2048);
    float4 wr0 = make_float4(0.f, 0.f, 0.f, 0.f), wr1 = wr0;
    if (nmax > 0) { wr0 = wsrc[tid]; wr1 = wsrc[tid + 256]; }

    ull acc[4][4];
#pragma unroll
    for (int j = 0; j < 4; j++)
#pragma unroll
        for (int u = 0; u < 4; u++) acc[j][u] = 0ull;

    for (int ln = 0; ln < nmax; ln++) {
        Wf4[ln & 1][sdst0] = wr0;
        Wf4[ln & 1][sdst1] = wr1;
        if (ln + 1 < nmax) {
            const float4* ws = wsrc + (size_t)(ln + 1) * 512;
            wr0 = ws[tid]; wr1 = ws[tid + 256];
        }
        __syncthreads();

        const float4* wb = &Wf4[ln & 1][oh * 34 + k];

        ull h[4][4];
#pragma unroll
        for (int d = 0; d < 8; d++) {
            float4 xq = *(const float4*)&xs[ln][d][4 * w];
            ull xd[4];
            xd[0] = pack2(xq.x); xd[1] = pack2(xq.y);
            xd[2] = pack2(xq.z); xd[3] = pack2(xq.w);
            ulonglong2 wv0 = *(const ulonglong2*)&wb[d * 68];
            ulonglong2 wv1 = *(const ulonglong2*)&wb[d * 68 + 17];
#pragma unroll
            for (int j = 0; j < 4; j++) {
                if (d == 0) {
                    h[j][0] = mul2(xd[j], wv0.x);
                    h[j][1] = mul2(xd[j], wv0.y);
                    h[j][2] = mul2(xd[j], wv1.x);
                    h[j][3] = mul2(xd[j], wv1.y);
                } else {
                    h[j][0] = fma2(xd[j], wv0.x, h[j][0]);
                    h[j][1] = fma2(xd[j], wv0.y, h[j][1]);
                    h[j][2] = fma2(xd[j], wv1.x, h[j][2]);
                    h[j][3] = fma2(xd[j], wv1.y, h[j][3]);
                }
            }
        }

#pragma unroll
        for (int j = 0; j < 4; j++) {
            uint4 st;
            float2 a0 = unpack2(h[j][0]);
            float2 a1 = unpack2(h[j][1]);
            float2 a2 = unpack2(h[j][2]);
            float2 a3 = unpack2(h[j][3]);
            st.x = cvtf16x2(a0.x, a0.y);
            st.y = cvtf16x2(a1.x, a1.y);
            st.z = cvtf16x2(a2.x, a2.y);
            st.w = cvtf16x2(a3.x, a3.y);
            acc[j][0] = add2(acc[j][0], h[j][0]);
            acc[j][1] = add2(acc[j][1], h[j][1]);
            acc[j][2] = add2(acc[j][2], h[j][2]);
            acc[j][3] = add2(acc[j][3], h[j][3]);
            *(uint4*)(g_hats + ((size_t)(bg0 + j) * 2048 + (size_t)(n0 + ln)) * 256
                      + (size_t)k * 16 + 8 * oh) = st;
        }
    }

#pragma unroll
    for (int j = 0; j < 4; j++) {
        float* pp = g_part + ((size_t)blockIdx.x * 64 + (size_t)(bg0 + j)) * 256
                    + (size_t)k * 16 + 8 * oh;
        float2 v0 = unpack2(acc[j][0]);
        float2 v1 = unpack2(acc[j][1]);
        float2 v2 = unpack2(acc[j][2]);
        float2 v3 = unpack2(acc[j][3]);
        *(float4*)(pp)     = make_float4(v0.x, v0.y, v1.x, v1.y);
        *(float4*)(pp + 4) = make_float4(v2.x, v2.y, v3.x, v3.y);
    }
}

// route v4: grid 1024 = (b<64)*(g<16), 256 thr (8 warps).
// Warp w owns n in [g*128 + w*16, +16): streams its 8KB through a private
// 4x1KB cp.async ring, depth 3, __syncwarp only. Epilogue: block reduction.
__global__ void __launch_bounds__(256) route_kernel() {
    __shared__ __align__(16) unsigned char hbuf[8][4][1024];  // 32 KB
    __shared__ float red[8][256];                             // 8 KB

    const int b = blockIdx.x >> 4, g = blockIdx.x & 15;
    const int w = threadIdx.x >> 5, l = threadIdx.x & 31;
    const int k = l & 15, oh = l >> 4;

    const unsigned char* gsrc = (const unsigned char*)g_hats
        + ((size_t)b * 2048 + (size_t)(g * 128 + w * 16)) * 512;  // warp's 8KB
    const unsigned sbase = (unsigned)__cvta_generic_to_shared(&hbuf[w][0][0]);
    const int l32 = l * 32;

    // prologue: issue slots 0..2 (1KB = 2 n each)
#pragma unroll
    for (int c = 0; c < 3; c++) {
        unsigned d = sbase + c * 1024 + l32;
        const unsigned char* s = gsrc + c * 1024 + l32;
        cp16(d, s);
        cp16(d + 16, s + 16);
        cp_commit();
    }

    ull rr[4];
    {
        const ull* rp = (const ull*)(g_route + ((size_t)b * 16 + k) * 16 + 8 * oh);
        rr[0] = rp[0]; rr[1] = rp[1]; rr[2] = rp[2]; rr[3] = rp[3];
    }

    ull acc[4] = {0ull, 0ull, 0ull, 0ull};
    const int loff = k * 32 + oh * 16;                 // byte offset in 512B row

#pragma unroll
    for (int it = 0; it < 8; it++) {
        int wg = 7 - it; if (wg > 2) wg = 2;
        cp_wait(wg);
        __syncwarp();     // slot it ready for all lanes; slot (it-1)&3 fully read
        if (it + 3 < 8) {
            unsigned d = sbase + ((it + 3) & 3) * 1024 + l32;
            const unsigned char* s = gsrc + (size_t)(it + 3) * 1024 + l32;
            cp16(d, s);
            cp16(d + 16, s + 16);
            cp_commit();
        }
        const unsigned char* buf = &hbuf[w][it & 3][0];
#pragma unroll
        for (int nl = 0; nl < 2; nl++) {
            uint4 v = *(const uint4*)(buf + nl * 512 + loff);
            ull hh[4];
            hh[0] = h2f2(v.x); hh[1] = h2f2(v.y); hh[2] = h2f2(v.z); hh[3] = h2f2(v.w);

            ull t = mul2(hh[0], rr[0]);
            ull u = mul2(hh[1], rr[1]);
            t = fma2(hh[2], rr[2], t);
            u = fma2(hh[3], rr[3], u);
            float2 q = unpack2(add2(t, u));
            float pb = q.x + q.y;
            pb += __shfl_xor_sync(0xffffffffu, pb, 16);    // combine o-halves
            float e = __expf(pb);                          // |bias| small: no max-sub
            float s = e;
            s += __shfl_xor_sync(0xffffffffu, s, 1);
            s += __shfl_xor_sync(0xffffffffu, s, 2);
            s += __shfl_xor_sync(0xffffffffu, s, 4);
            s += __shfl_xor_sync(0xffffffffu, s, 8);
            ull c2 = pack2(__fdividef(e, s));
            acc[0] = fma2(c2, hh[0], acc[0]);
            acc[1] = fma2(c2, hh[1], acc[1]);
            acc[2] = fma2(c2, hh[2], acc[2]);
            acc[3] = fma2(c2, hh[3], acc[3]);
        }
    }

    // cross-warp reduction via smem
    {
        float* dst = &red[w][k * 16 + 8 * oh];
        float2 v0 = unpack2(acc[0]);
        float2 v1 = unpack2(acc[1]);
        float2 v2 = unpack2(acc[2]);
        float2 v3 = unpack2(acc[3]);
        *(float4*)(dst)     = make_float4(v0.x, v0.y, v1.x, v1.y);
        *(float4*)(dst + 4) = make_float4(v2.x, v2.y, v3.x, v3.y);
    }
    __syncthreads();
    {
        const int t = threadIdx.x;
        float s = 0.f;
#pragma unroll
        for (int ww = 0; ww < 8; ww++) s += red[ww][t];
        g_part2[((size_t)g * 64 + b) * 256 + t] = s;
    }
}

// Reduce cnt chunks (g_part if src==0 else g_part2), squash, route/output.
__global__ void __launch_bounds__(1024) squash_kernel(int src, int cnt, float scale,
                                                      int mode, float* __restrict__ out) {
    __shared__ float red[4][256];
    const int tid = threadIdx.x, q = tid >> 8, t = tid & 255;
    const int b = blockIdx.x;
    const float* base = (src == 0 ? g_part : g_part2) + (size_t)b * 256 + t;
    float s = 0.f;
#pragma unroll 4
    for (int j = q; j < cnt; j += 4)
        s += base[(size_t)j * 16384];
    red[q][t] = s;
    __syncthreads();
    if (tid < 256) {
        s = (red[0][t] + red[1][t]) + (red[2][t] + red[3][t]);
        s *= scale;
        float s2 = s * s;
        s2 += __shfl_xor_sync(0xffffffffu, s2, 1);
        s2 += __shfl_xor_sync(0xffffffffu, s2, 2);
        s2 += __shfl_xor_sync(0xffffffffu, s2, 4);
        s2 += __shfl_xor_sync(0xffffffffu, s2, 8);
        float sc = s2 / ((1.0f + s2) * sqrtf(s2));
        float v = sc * s;
        int idx = b * 256 + t;
        if (mode == 0)      g_route[idx] = v;    // route = out0
        else if (mode == 1) g_route[idx] += v;   // route = out0 + out1
        else                out[idx] = v;        // final [B,16,16]
    }
}

extern "C" void kernel_launch(void* const* d_in, const int* in_sizes, int n_in,
                              void* d_out, int out_size) {
    const float* x = (const float*)d_in[0];   // [64, 2048, 8]
    const float* W = (const float*)d_in[1];   // [2048, 16, 8, 16]
    float* out = (float*)d_out;               // [64, 16, 16]
    (void)in_sizes; (void)n_in; (void)out_size;

    noop_kernel<<<1, 1>>>();                                  // profiler alignment
    pass1_kernel<<<dim3(NBLK, 2), 256>>>(x, W);               // hats fp16 + s0 partials
    squash_kernel<<<64, 1024>>>(0, NBLK, 1.0f / 16.0f, 0, out); // out0 -> route
    route_kernel<<<1024, 256>>>();                            // 4th launch (profiled)
    squash_kernel<<<64, 1024>>>(1, 16, 1.0f, 1, out);         // route += out1
    route_kernel<<<1024, 256>>>();                            // s2 partials
    squash_kernel<<<64, 1024>>>(1, 16, 1.0f, 2, out);         // final output
}